// round 4
// baseline (speedup 1.0000x reference)
#include <cuda_runtime.h>
#include <cstdint>
#include <math.h>

#define CNUM 128
#define SMAX 401
#define EFLOOR (-(1 << 28))
#define KST   3
#define HALO  6            // 2*KST
#define VALID 26           // 32 - HALO
#define NWARPS 16          // ceil(401/26)
#define NTH   (NWARPS * 32)

// Scratch: softmax(y_pred) rows, [B][T][C] = 64*2000*128 floats (64 MB).
__device__ float g_p[64 * 2000 * CNUM];

// ---------------------------------------------------------------------------
// Kernel 1: row softmax over C=128. One warp per (b,t) row.
// ---------------------------------------------------------------------------
__global__ void softmax_kernel(const float* __restrict__ y, int rows) {
    int gw   = (blockIdx.x * blockDim.x + threadIdx.x) >> 5;
    int lane = threadIdx.x & 31;
    if (gw >= rows) return;
    float4 v = reinterpret_cast<const float4*>(y)[(size_t)gw * 32 + lane];
    float m = fmaxf(fmaxf(v.x, v.y), fmaxf(v.z, v.w));
#pragma unroll
    for (int o = 16; o; o >>= 1) m = fmaxf(m, __shfl_xor_sync(0xffffffffu, m, o));
    float e0 = __expf(v.x - m), e1 = __expf(v.y - m);
    float e2 = __expf(v.z - m), e3 = __expf(v.w - m);
    float sm = e0 + e1 + e2 + e3;
#pragma unroll
    for (int o = 16; o; o >>= 1) sm += __shfl_xor_sync(0xffffffffu, sm, o);
    float inv = __frcp_rn(sm);
    float4 o4 = make_float4(e0 * inv, e1 * inv, e2 * inv, e3 * inv);
    reinterpret_cast<float4*>(g_p)[(size_t)gw * 32 + lane] = o4;
}

// ---------------------------------------------------------------------------
// Kernel 2: CTC alpha recursion, register-resident with overlapped halo.
// One CTA per batch element. Warp w lane l owns state s = 26w + l - 6
// (lanes 0..5 = halo duplicating warp w-1's top states; negative states
// self-maintain the zero floor). alpha = (mantissa float in [1,2) or 0,
// int exponent; EFLOOR = zero). 3 steps per barrier: shuffles exchange
// neighbors in-warp; halo consumed 2 lanes/step; top 6 lanes publish to
// shared, bottom 6 refresh after the barrier. Softmax rows streamed
// through an 8-stage shared ring via cp.async (per-row commit groups).
// ---------------------------------------------------------------------------
__device__ __forceinline__ void cp_async16(uint32_t saddr, const void* g) {
    asm volatile("cp.async.cg.shared.global [%0], [%1], 16;" :: "r"(saddr), "l"(g));
}

__global__ __launch_bounds__(NTH) void ctc_kernel(
    const int* __restrict__ labels, const int* __restrict__ in_len,
    const int* __restrict__ lab_len, float* __restrict__ out, int T, int L)
{
    __shared__ float s_y[8][CNUM];     // ring of softmax rows
    __shared__ int2  s_al[SMAX];       // published alpha (halo exchange + readout)

    const int b    = blockIdx.x;
    const int tid  = threadIdx.x;
    const int wid  = tid >> 5;
    const int lane = tid & 31;
    const float* pb = g_p + (size_t)b * T * CNUM;
    const int tend  = min(T, in_len[b]);

    const int s = wid * VALID + lane - HALO;
    int  ext_c = CNUM - 1;              // blank
    bool skip  = false;
    if (s >= 0 && s < SMAX && (s & 1)) {
        int v = labels[b * L + (s >> 1)];
        ext_c = (v < 0) ? 0 : v;        // ref: lab = where(y_true<0, 0, y_true)
        if (s >= 3) {
            int v2 = labels[b * L + (s >> 1) - 1];
            v2 = (v2 < 0) ? 0 : v2;
            skip = (ext_c != v2);
        }
    }

    const bool loader = (wid == 0);
    uint32_t smy = (uint32_t)__cvta_generic_to_shared(&s_y[0][0]);

    // Prologue: rows 0..5 issued; rows 0..3 complete on entry (2 outstanding).
    if (loader) {
#pragma unroll
        for (int d = 0; d < 6; ++d) {
            if (d < T) cp_async16(smy + (uint32_t)(d * CNUM + lane * 4) * 4,
                                  pb + (size_t)d * CNUM + lane * 4);
            asm volatile("cp.async.commit_group;");
        }
        asm volatile("cp.async.wait_group 2;");
    }
    __syncthreads();

    // t = 0 init (register alpha)
    float am = 0.f; int ae = EFLOOR;
    {
        float v = 0.f;
        if (s == 0)      v = s_y[0][CNUM - 1];
        else if (s == 1) v = s_y[0][ext_c];
        if (v > 0.f) {
            int bits = __float_as_int(v);
            am = __int_as_float((bits & 0x007FFFFF) | 0x3F800000);
            ae = (bits >> 23) - 127;
        }
    }

    // Invariant at block entry: rows [t0 .. t0+2] complete, rows t0+3,t0+4
    // outstanding. Block reads stages t0..t0+2 (mod 8), issues rows
    // t0+5..t0+7 into stages t0+5..t0+7 (mod 8) -- disjoint.
    for (int t0 = 1; t0 < tend; t0 += KST) {
#pragma unroll
        for (int j = 0; j < KST; ++j) {
            const int t = t0 + j;
            const float py = s_y[t & 7][ext_c];
            float m1 = __shfl_up_sync(0xffffffffu, am, 1);
            int   e1 = __shfl_up_sync(0xffffffffu, ae, 1);
            float m2 = __shfl_up_sync(0xffffffffu, am, 2);
            int   e2 = __shfl_up_sync(0xffffffffu, ae, 2);
            if (!skip) { m2 = 0.f; e2 = EFLOOR; }
            int em = max(ae, max(e1, e2));
            float f0 = __int_as_float(max(ae - em + 127, 0) << 23); // exact 2^(e-em)
            float f1 = __int_as_float(max(e1 - em + 127, 0) << 23);
            float f2 = __int_as_float(max(e2 - em + 127, 0) << 23);
            float v  = (am * f0 + m1 * f1 + m2 * f2) * py;
            int bits = __float_as_int(v);                 // v >= 0
            bool z   = (v == 0.f);
            float nm = z ? 0.f   : __int_as_float((bits & 0x007FFFFF) | 0x3F800000);
            int   ne = z ? EFLOOR : ((bits >> 23) - 127 + em);
            if (t < tend) { am = nm; ae = ne; }           // freeze past seq end
        }
        // Publish top HALO lanes (they are next warp's halo states)
        if (lane >= VALID && s < SMAX)
            s_al[s] = make_int2(__float_as_int(am), ae);
        // Prefetch rows t0+5 .. t0+7
        if (loader) {
#pragma unroll
            for (int jj = 0; jj < KST; ++jj) {
                int tn = t0 + 5 + jj;
                if (tn < T) cp_async16(smy + (uint32_t)((tn & 7) * CNUM + lane * 4) * 4,
                                       pb + (size_t)tn * CNUM + lane * 4);
                asm volatile("cp.async.commit_group;");
            }
            asm volatile("cp.async.wait_group 2;");
        }
        __syncthreads();
        // Refresh halo lanes from previous warp's published values
        if (lane < HALO && s >= 0) {
            int2 hv = s_al[s];
            am = __int_as_float(hv.x);
            ae = hv.y;
        }
    }

    // Final full publish (valid lanes cover all states)
    if (lane >= HALO && s < SMAX)
        s_al[s] = make_int2(__float_as_int(am), ae);
    __syncthreads();

    if (tid == 0) {
        int se = 2 * lab_len[b];
        int sp = (se > 0) ? (se - 1) : 0;
        int2 Al = s_al[se];
        int2 Ap = s_al[sp];
        double el = (double)Al.y, ep = (double)Ap.y;
        double em = fmax(el, ep);
        double dl = fmax(el - em, -1100.0);
        double dp = fmax(ep - em, -1100.0);
        double val = (double)__int_as_float(Al.x) * exp2(dl)
                   + (double)__int_as_float(Ap.x) * exp2(dp);
        out[b] = (float)(-(log(val) + em * 0.6931471805599453));
    }
}

// ---------------------------------------------------------------------------
extern "C" void kernel_launch(void* const* d_in, const int* in_sizes, int n_in,
                              void* d_out, int out_size) {
    const float* y  = (const float*)d_in[0];
    const int*   yt = (const int*)d_in[1];
    const int*   il = (const int*)d_in[2];
    const int*   ll = (const int*)d_in[3];
    int B = in_sizes[2];
    int L = in_sizes[1] / B;
    int rows = in_sizes[0] / CNUM;   // B*T
    int T = rows / B;

    int sm_blocks = (rows * 32 + 255) / 256;
    softmax_kernel<<<sm_blocks, 256>>>(y, rows);
    ctc_kernel<<<B, NTH>>>(yt, il, ll, (float*)d_out, T, L);
}

// round 5
// speedup vs baseline: 2.1575x; 2.1575x over previous
#include <cuda_runtime.h>
#include <cstdint>
#include <math.h>

#define CNUM 128
#define SMAX 401
#define EFLOOR (-(1 << 28))
#define KST   3
#define HALO  6            // 2*KST
#define VALID 26           // 32 - HALO
#define NWARPS 16          // ceil(401/26)
#define NTH   (NWARPS * 32)
#define RING  16           // ring stages (rows)

// Scratch: softmax(y_pred) rows, [B][T][C] = 64*2000*128 floats (64 MB).
__device__ float g_p[64 * 2000 * CNUM];

// ---------------------------------------------------------------------------
// Kernel 1: row softmax over C=128. One warp per (b,t) row.
// ---------------------------------------------------------------------------
__global__ void softmax_kernel(const float* __restrict__ y, int rows) {
    int gw   = (blockIdx.x * blockDim.x + threadIdx.x) >> 5;
    int lane = threadIdx.x & 31;
    if (gw >= rows) return;
    float4 v = reinterpret_cast<const float4*>(y)[(size_t)gw * 32 + lane];
    float m = fmaxf(fmaxf(v.x, v.y), fmaxf(v.z, v.w));
#pragma unroll
    for (int o = 16; o; o >>= 1) m = fmaxf(m, __shfl_xor_sync(0xffffffffu, m, o));
    float e0 = __expf(v.x - m), e1 = __expf(v.y - m);
    float e2 = __expf(v.z - m), e3 = __expf(v.w - m);
    float sm = e0 + e1 + e2 + e3;
#pragma unroll
    for (int o = 16; o; o >>= 1) sm += __shfl_xor_sync(0xffffffffu, sm, o);
    float inv = __frcp_rn(sm);
    float4 o4 = make_float4(e0 * inv, e1 * inv, e2 * inv, e3 * inv);
    reinterpret_cast<float4*>(g_p)[(size_t)gw * 32 + lane] = o4;
}

// ---------------------------------------------------------------------------
// Kernel 2: CTC alpha recursion, register-resident with overlapped halo.
// One CTA per batch element. Warp w lane l owns state s = 26w + l - 6
// (lanes 0..5 = halo duplicating warp w-1's top states; negative states
// self-maintain the zero floor). alpha = (mantissa in [1,2) or 0, int
// exponent; EFLOOR = zero). 3 steps per barrier via in-warp shuffles.
// Softmax rows streamed through a 16-stage ring via cp.async with
// prefetch distance 12 rows (~7 blocks of latency cover).
// ---------------------------------------------------------------------------
__device__ __forceinline__ void cp_async16(uint32_t saddr, const void* g) {
    asm volatile("cp.async.cg.shared.global [%0], [%1], 16;" :: "r"(saddr), "l"(g));
}

__global__ __launch_bounds__(NTH) void ctc_kernel(
    const int* __restrict__ labels, const int* __restrict__ in_len,
    const int* __restrict__ lab_len, float* __restrict__ out, int T, int L)
{
    __shared__ float s_y[RING][CNUM];   // ring of softmax rows (8 KB)
    __shared__ int2  s_al[SMAX];        // published alpha (halo exchange + readout)

    const int b    = blockIdx.x;
    const int tid  = threadIdx.x;
    const int wid  = tid >> 5;
    const int lane = tid & 31;
    const float* pb = g_p + (size_t)b * T * CNUM;
    const int tend  = min(T, in_len[b]);

    const int s = wid * VALID + lane - HALO;
    int  ext_c = CNUM - 1;              // blank
    bool skip  = false;
    if (s >= 0 && s < SMAX && (s & 1)) {
        int v = labels[b * L + (s >> 1)];
        ext_c = (v < 0) ? 0 : v;        // ref: lab = where(y_true<0, 0, y_true)
        if (s >= 3) {
            int v2 = labels[b * L + (s >> 1) - 1];
            v2 = (v2 < 0) ? 0 : v2;
            skip = (ext_c != v2);
        }
    }

    const bool loader = (wid == 0);
    uint32_t smy = (uint32_t)__cvta_generic_to_shared(&s_y[0][0]);

    // Prologue: rows 0..12 issued (one commit group per row, empty past T).
    // wait_group 9 -> rows 0..3 complete.
    if (loader) {
#pragma unroll
        for (int d = 0; d < 13; ++d) {
            if (d < T) cp_async16(smy + (uint32_t)(d * CNUM + lane * 4) * 4,
                                  pb + (size_t)d * CNUM + lane * 4);
            asm volatile("cp.async.commit_group;");
        }
        asm volatile("cp.async.wait_group 9;");
    }
    __syncthreads();

    // t = 0 init (register alpha)
    float am = 0.f; int ae = EFLOOR;
    {
        float v = 0.f;
        if (s == 0)      v = s_y[0][CNUM - 1];
        else if (s == 1) v = s_y[0][ext_c];
        if (v > 0.f) {
            int bits = __float_as_int(v);
            am = __int_as_float((bits & 0x007FFFFF) | 0x3F800000);
            ae = (bits >> 23) - 127;
        }
    }

    // Invariant at block entry: rows <= t0+2 complete & visible.
    // Block t0: reads stages t0..t0+2 (mod 16); issues rows t0+12..t0+14
    // (stages disjoint, distance 12); wait_group 9 -> rows <= t0+5 complete.
    for (int t0 = 1; t0 < tend; t0 += KST) {
        // Hoist the 3 prob loads off the shuffle critical chain.
        float py[KST];
#pragma unroll
        for (int j = 0; j < KST; ++j)
            py[j] = s_y[(t0 + j) & (RING - 1)][ext_c];

#pragma unroll
        for (int j = 0; j < KST; ++j) {
            const int t = t0 + j;
            float m1 = __shfl_up_sync(0xffffffffu, am, 1);
            int   e1 = __shfl_up_sync(0xffffffffu, ae, 1);
            float m2 = __shfl_up_sync(0xffffffffu, am, 2);
            int   e2 = __shfl_up_sync(0xffffffffu, ae, 2);
            if (!skip) { m2 = 0.f; e2 = EFLOOR; }
            int em = max(ae, max(e1, e2));
            float f0 = __int_as_float(max(ae - em + 127, 0) << 23); // exact 2^(e-em)
            float f1 = __int_as_float(max(e1 - em + 127, 0) << 23);
            float f2 = __int_as_float(max(e2 - em + 127, 0) << 23);
            float v  = (am * f0 + m1 * f1 + m2 * f2) * py[j];
            int bits = __float_as_int(v);                 // v >= 0
            bool z   = (v == 0.f);
            float nm = z ? 0.f   : __int_as_float((bits & 0x007FFFFF) | 0x3F800000);
            int   ne = z ? EFLOOR : ((bits >> 23) - 127 + em);
            if (t < tend) { am = nm; ae = ne; }           // freeze past seq end
        }
        // Publish top HALO lanes (next warp's halo states)
        if (lane >= VALID && s < SMAX)
            s_al[s] = make_int2(__float_as_int(am), ae);
        // Prefetch rows t0+12 .. t0+14, then ensure rows <= t0+5 complete.
        if (loader) {
#pragma unroll
            for (int jj = 0; jj < KST; ++jj) {
                int tn = t0 + 12 + jj;
                if (tn < T) cp_async16(smy + (uint32_t)((tn & (RING - 1)) * CNUM + lane * 4) * 4,
                                       pb + (size_t)tn * CNUM + lane * 4);
                asm volatile("cp.async.commit_group;");
            }
            asm volatile("cp.async.wait_group 9;");
        }
        __syncthreads();
        // Refresh halo lanes from previous warp's published values
        if (lane < HALO && s >= 0) {
            int2 hv = s_al[s];
            am = __int_as_float(hv.x);
            ae = hv.y;
        }
    }

    // Final full publish (valid lanes cover all states)
    if (lane >= HALO && s < SMAX)
        s_al[s] = make_int2(__float_as_int(am), ae);
    __syncthreads();

    if (tid == 0) {
        int se = 2 * lab_len[b];
        int sp = (se > 0) ? (se - 1) : 0;
        int2 Al = s_al[se];
        int2 Ap = s_al[sp];
        double el = (double)Al.y, ep = (double)Ap.y;
        double em = fmax(el, ep);
        double dl = fmax(el - em, -1100.0);
        double dp = fmax(ep - em, -1100.0);
        double val = (double)__int_as_float(Al.x) * exp2(dl)
                   + (double)__int_as_float(Ap.x) * exp2(dp);
        out[b] = (float)(-(log(val) + em * 0.6931471805599453));
    }
}

// ---------------------------------------------------------------------------
extern "C" void kernel_launch(void* const* d_in, const int* in_sizes, int n_in,
                              void* d_out, int out_size) {
    const float* y  = (const float*)d_in[0];
    const int*   yt = (const int*)d_in[1];
    const int*   il = (const int*)d_in[2];
    const int*   ll = (const int*)d_in[3];
    int B = in_sizes[2];
    int L = in_sizes[1] / B;
    int rows = in_sizes[0] / CNUM;   // B*T
    int T = rows / B;

    int sm_blocks = (rows * 32 + 255) / 256;
    softmax_kernel<<<sm_blocks, 256>>>(y, rows);
    ctc_kernel<<<B, NTH>>>(yt, il, ll, (float*)d_out, T, L);
}

// round 6
// speedup vs baseline: 2.7360x; 1.2681x over previous
#include <cuda_runtime.h>
#include <cstdint>
#include <math.h>

#define CNUM  128
#define SMAX  401
#define KST   6              // steps per barrier = halo lanes
#define VALID 26             // 32 - KST
#define NW    8              // warps: 8*26*2 = 416 states >= 401
#define NTH   (NW * 32)
#define RING  32             // ring stages (rows)
#define NPAIR (NW * VALID)   // 208
#define EFL   (-32768)       // exponent floor (int16 min)

// Scratch: softmax(y_pred) rows, [B][T][C] = 64*2000*128 floats (64 MB).
__device__ float g_p[64 * 2000 * CNUM];

// ---------------------------------------------------------------------------
// Kernel 1: row softmax over C=128. One warp per (b,t) row.
// ---------------------------------------------------------------------------
__global__ void softmax_kernel(const float* __restrict__ y, int rows) {
    int gw   = (blockIdx.x * blockDim.x + threadIdx.x) >> 5;
    int lane = threadIdx.x & 31;
    if (gw >= rows) return;
    float4 v = reinterpret_cast<const float4*>(y)[(size_t)gw * 32 + lane];
    float m = fmaxf(fmaxf(v.x, v.y), fmaxf(v.z, v.w));
#pragma unroll
    for (int o = 16; o; o >>= 1) m = fmaxf(m, __shfl_xor_sync(0xffffffffu, m, o));
    float e0 = __expf(v.x - m), e1 = __expf(v.y - m);
    float e2 = __expf(v.z - m), e3 = __expf(v.w - m);
    float sm = e0 + e1 + e2 + e3;
#pragma unroll
    for (int o = 16; o; o >>= 1) sm += __shfl_xor_sync(0xffffffffu, sm, o);
    float inv = __frcp_rn(sm);
    float4 o4 = make_float4(e0 * inv, e1 * inv, e2 * inv, e3 * inv);
    reinterpret_cast<float4*>(g_p)[(size_t)gw * 32 + lane] = o4;
}

// ---------------------------------------------------------------------------
// Kernel 2: CTC alpha recursion, 2 states per lane (even=blank, odd=label).
// Lane l of warp w owns pair p = 26w + l - 6 (lanes 0..5 = halo of warp w-1;
// p < 0 lanes self-maintain the floor). alpha = (fp32 mantissa in [1,2),
// int exponent; floor -32768 ~ zero, clamped away by exponent alignment).
// Even state 2p depends on {2p, 2p-1}; odd 2p+1 on {2p+1, 2p(own), 2p-1}.
// -> only neighbor ODD value crosses lanes: ONE shuffle per step, packed
// (exp<<16 | mant16). 6 steps per barrier. Softmax rows stream through a
// 32-stage cp.async ring, prefetch distance ~18 rows.
// ---------------------------------------------------------------------------
__device__ __forceinline__ void cp_async16(uint32_t saddr, const void* g) {
    asm volatile("cp.async.cg.shared.global [%0], [%1], 16;" :: "r"(saddr), "l"(g));
}
__device__ __forceinline__ float exp2i_clamp(int d) {
    // exact 2^d for d in [-127,0]; 0 for d <= -127 (bit-constructed, no I2F)
    return __int_as_float(max(d + 127, 0) << 23);
}

__global__ __launch_bounds__(NTH) void ctc_kernel(
    const int* __restrict__ labels, const int* __restrict__ in_len,
    const int* __restrict__ lab_len, float* __restrict__ out, int T, int L)
{
    __shared__ float s_y[RING][CNUM];     // 16 KB ring of softmax rows
    __shared__ int4  s_pair[NPAIR];       // halo publish (mE,eE,mL,eL)
    __shared__ int2  s_al[2 * NPAIR];     // final readout

    const int b    = blockIdx.x;
    const int tid  = threadIdx.x;
    const int wid  = tid >> 5;
    const int lane = tid & 31;
    const float* pb = g_p + (size_t)b * T * CNUM;
    const int tend  = min(T, in_len[b]);

    const int p = wid * VALID + lane - KST;      // pair index
    int  ext_c = CNUM - 1;                       // odd-state class (label)
    bool skip  = false;
    if (p >= 0 && 2 * p + 1 < SMAX) {
        int v = labels[b * L + p];
        ext_c = (v < 0) ? 0 : v;
        if (p >= 1) {
            int v2 = labels[b * L + p - 1];
            v2 = (v2 < 0) ? 0 : v2;
            skip = (ext_c != v2);
        }
    }

    const bool loader = (wid == 0);
    uint32_t smy = (uint32_t)__cvta_generic_to_shared(&s_y[0][0]);

    // Prologue: rows 0..23 issued (empty groups past T). wait 17 -> rows 0..6 done.
    if (loader) {
#pragma unroll
        for (int d = 0; d < 24; ++d) {
            if (d < T) cp_async16(smy + (uint32_t)(d * CNUM + lane * 4) * 4,
                                  pb + (size_t)d * CNUM + lane * 4);
            asm volatile("cp.async.commit_group;");
        }
        asm volatile("cp.async.wait_group 17;");
    }
    __syncthreads();

    // t = 0 init
    float mE = 1.0f, mL = 1.0f;
    int   eE = EFL,  eL = EFL;
    if (p == 0) {
        float vE = s_y[0][CNUM - 1];
        float vL = s_y[0][ext_c];
        int bE = __float_as_int(vE), bL = __float_as_int(vL);
        if (vE > 0.f) { mE = __int_as_float((bE & 0x7FFFFF) | 0x3F800000); eE = (bE >> 23) - 127; }
        if (vL > 0.f) { mL = __int_as_float((bL & 0x7FFFFF) | 0x3F800000); eL = (bL >> 23) - 127; }
    }
    unsigned wOdd = ((unsigned)(eL & 0xFFFF) << 16) |
                    ((unsigned)(__float_as_int(mL) >> 7) & 0xFFFFu);

    // One recursion step at time t (no bounds guard; caller controls range).
    auto step = [&](int t, float pyB, float pyL) {
        unsigned w1 = __shfl_up_sync(0xffffffffu, wOdd, 1);
        int   e1 = ((int)w1) >> 16;
        float m1 = __int_as_float(((w1 << 7) & 0x007FFF80u) | 0x3F800000u);
        // even state 2p: (aE + a_{2p-1}) * p_blank
        int   emE = max(eE, e1);
        float vE  = (mE * exp2i_clamp(eE - emE) + m1 * exp2i_clamp(e1 - emE)) * pyB;
        // odd state 2p+1: (aL + aE_old + skip*a_{2p-1}) * p_label
        int   e2  = skip ? e1 : (-(1 << 30));
        float m2  = skip ? m1 : 0.f;
        int   emL = max(max(eL, eE), e2);
        float vL  = (mL * exp2i_clamp(eL - emL) + mE * exp2i_clamp(eE - emL)
                   + m2 * exp2i_clamp(e2 - emL)) * pyL;
        // repack (v>=0; subnormal/zero v decays to ~floor, provably negligible)
        int bE = __float_as_int(vE);
        eE = max((bE >> 23) - 127 + emE, EFL);
        mE = __int_as_float((bE & 0x7FFFFF) | 0x3F800000);
        int bL = __float_as_int(vL);
        eL = max((bL >> 23) - 127 + emL, EFL);
        mL = __int_as_float((bL & 0x7FFFFF) | 0x3F800000);
        wOdd = ((unsigned)(eL & 0xFFFF) << 16) | ((unsigned)(bL >> 7) & 0xFFFFu);
    };

    // Full blocks of 6 steps (guard-free). Invariant at entry: rows t0..t0+5
    // complete & visible; prefetch row base t0+23; wait 17 -> rows <= t0+11.
    int t0 = 1;
    for (; t0 + KST <= tend; t0 += KST) {
        float py[KST][2];
#pragma unroll
        for (int j = 0; j < KST; ++j) {
            py[j][0] = s_y[(t0 + j) & (RING - 1)][CNUM - 1];
            py[j][1] = s_y[(t0 + j) & (RING - 1)][ext_c];
        }
#pragma unroll
        for (int j = 0; j < KST; ++j)
            step(t0 + j, py[j][0], py[j][1]);
        // publish top KST lanes (next warp's halo pairs)
        if (lane >= VALID)
            s_pair[p] = make_int4(__float_as_int(mE), eE, __float_as_int(mL), eL);
        if (loader) {
#pragma unroll
            for (int jj = 0; jj < KST; ++jj) {
                int tn = t0 + 24 + jj - 1;   // rows t0+23 .. t0+28
                if (tn < T) cp_async16(smy + (uint32_t)((tn & (RING - 1)) * CNUM + lane * 4) * 4,
                                       pb + (size_t)tn * CNUM + lane * 4);
                asm volatile("cp.async.commit_group;");
            }
            asm volatile("cp.async.wait_group 17;");
        }
        __syncthreads();
        // refresh halo lanes
        if (lane < KST && p >= 0) {
            int4 hv = s_pair[p];
            mE = __int_as_float(hv.x); eE = hv.y;
            mL = __int_as_float(hv.z); eL = hv.w;
            wOdd = ((unsigned)(eL & 0xFFFF) << 16) |
                   ((unsigned)(hv.z >> 7) & 0xFFFFu);
        }
    }
    // Tail (< 6 steps; halo fresh, rows <= t0+11 complete)
    for (int t = t0; t < tend; ++t)
        step(t, s_y[t & (RING - 1)][CNUM - 1], s_y[t & (RING - 1)][ext_c]);

    // Final publish from valid lanes
    if (lane >= KST) {
        s_al[2 * p]     = make_int2(__float_as_int(mE), eE);
        s_al[2 * p + 1] = make_int2(__float_as_int(mL), eL);
    }
    __syncthreads();

    if (tid == 0) {
        int se = 2 * lab_len[b];
        int sp = (se > 0) ? (se - 1) : 0;
        int2 Al = s_al[se];
        int2 Ap = s_al[sp];
        double el = (double)Al.y, ep = (double)Ap.y;
        double em = fmax(el, ep);
        double dl = fmax(el - em, -1100.0);
        double dp = fmax(ep - em, -1100.0);
        double val = (double)__int_as_float(Al.x) * exp2(dl)
                   + (double)__int_as_float(Ap.x) * exp2(dp);
        out[b] = (float)(-(log(val) + em * 0.6931471805599453));
    }
}

// ---------------------------------------------------------------------------
extern "C" void kernel_launch(void* const* d_in, const int* in_sizes, int n_in,
                              void* d_out, int out_size) {
    const float* y  = (const float*)d_in[0];
    const int*   yt = (const int*)d_in[1];
    const int*   il = (const int*)d_in[2];
    const int*   ll = (const int*)d_in[3];
    int B = in_sizes[2];
    int L = in_sizes[1] / B;
    int rows = in_sizes[0] / CNUM;   // B*T
    int T = rows / B;

    int sm_blocks = (rows * 32 + 255) / 256;
    softmax_kernel<<<sm_blocks, 256>>>(y, rows);
    ctc_kernel<<<B, NTH>>>(yt, il, ll, (float*)d_out, T, L);
}

// round 8
// speedup vs baseline: 3.7497x; 1.3705x over previous
#include <cuda_runtime.h>
#include <cstdint>
#include <math.h>

#define CNUM   128
#define SMAX   401
#define KST    6               // steps per barrier = halo lanes
#define VALID  26              // 32 - KST
#define NW     8               // 8*26 = 208 pairs >= 201
#define NTH    (NW * 32)       // 256
#define NPAIR  (NW * VALID)    // 208
#define RING   32
#define MARGIN 16
#define PRO    26              // prologue rows issued
#define WGRP   19              // wait_group depth

// Scratch: softmax(y_pred) rows, [B][T][C] = 64*2000*128 floats (64 MB).
__device__ float g_p[64 * 2000 * CNUM];

// ---------------------------------------------------------------------------
// Kernel 1: row softmax over C=128. One warp per (b,t) row.
// ---------------------------------------------------------------------------
__global__ void softmax_kernel(const float* __restrict__ y, int rows) {
    int gw   = (blockIdx.x * blockDim.x + threadIdx.x) >> 5;
    int lane = threadIdx.x & 31;
    if (gw >= rows) return;
    float4 v = reinterpret_cast<const float4*>(y)[(size_t)gw * 32 + lane];
    float m = fmaxf(fmaxf(v.x, v.y), fmaxf(v.z, v.w));
#pragma unroll
    for (int o = 16; o; o >>= 1) m = fmaxf(m, __shfl_xor_sync(0xffffffffu, m, o));
    float e0 = __expf(v.x - m), e1 = __expf(v.y - m);
    float e2 = __expf(v.z - m), e3 = __expf(v.w - m);
    float sm = e0 + e1 + e2 + e3;
#pragma unroll
    for (int o = 16; o; o >>= 1) sm += __shfl_xor_sync(0xffffffffu, sm, o);
    float inv = __frcp_rn(sm);
    float4 o4 = make_float4(e0 * inv, e1 * inv, e2 * inv, e3 * inv);
    reinterpret_cast<float4*>(g_p)[(size_t)gw * 32 + lane] = o4;
}

// ---------------------------------------------------------------------------
// Kernel 2: CTC alpha recursion, block-scaled registers with a tight window.
// Lane owns pair p = 26w + lane - 6 (even 2p = blank, odd 2p+1 = label;
// lanes 0..5 = halo of prev warp). Pair stored as raw floats (mE, mL) at
// per-lane scale 2^ref, constant for 6 steps. At each boundary: halo
// refresh, ref := (8-lane window max of current exponents) + 16, exact
// two-factor re-base, neighbor conversion factors. Window covers every
// value reachable in 6 steps (influence <= 6 lanes) => no overflow; flush
// threshold ~110 bits below a 16-state-local max => no genuine-value loss.
// Inner step: 1 shuffle + ~9 FMA-pipe ops. cp.async ring depth 32,
// prefetch distance 19 groups.
// ---------------------------------------------------------------------------
__device__ __forceinline__ void cp_async16(uint32_t saddr, const void* g) {
    asm volatile("cp.async.cg.shared.global [%0], [%1], 16;" :: "r"(saddr), "l"(g));
}
__device__ __forceinline__ float pw2c(int d) {   // exact 2^clamp(d,-127,127)
    return __int_as_float((min(max(d, -127), 127) + 127) << 23);
}

__global__ __launch_bounds__(NTH) void ctc_kernel(
    const int* __restrict__ labels, const int* __restrict__ in_len,
    const int* __restrict__ lab_len, float* __restrict__ out, int T, int L)
{
    __shared__ float s_y[RING][CNUM];     // 16 KB ring
    __shared__ int4  s_pair[2][NPAIR];    // (mE bits, mL bits, ref, pad)
    __shared__ int2  s_al[2 * NPAIR];     // final readout (m bits, ref)

    const int b    = blockIdx.x;
    const int tid  = threadIdx.x;
    const int wid  = tid >> 5;
    const int lane = tid & 31;
    const float* pb = g_p + (size_t)b * T * CNUM;
    const int tend  = min(T, in_len[b]);

    const int p = wid * VALID + lane - KST;
    int  ext_c = CNUM - 1;
    bool skip  = false;
    if (p >= 0 && 2 * p + 1 < SMAX) {
        int v = labels[b * L + p];
        ext_c = (v < 0) ? 0 : v;
        if (p >= 1) {
            int v2 = labels[b * L + p - 1];
            v2 = (v2 < 0) ? 0 : v2;
            skip = (ext_c != v2);
        }
    }

    const bool loader = (wid == 0);
    uint32_t smy = (uint32_t)__cvta_generic_to_shared(&s_y[0][0]);

    // Prologue: rows 0..25 issued; wait 19 -> rows 0..6 complete.
    if (loader) {
#pragma unroll
        for (int d = 0; d < PRO; ++d) {
            if (d < T) cp_async16(smy + (uint32_t)(d * CNUM + lane * 4) * 4,
                                  pb + (size_t)d * CNUM + lane * 4);
            asm volatile("cp.async.commit_group;");
        }
        asm volatile("cp.async.wait_group 19;");
    }
    __syncthreads();

    // t = 0 init
    float mE = 0.f, mL = 0.f;
    int   ref = 0;
    if (p == 0) { mE = s_y[0][CNUM - 1]; mL = s_y[0][ext_c]; }

    // pre-loop publish (parity 0)
    if (lane >= VALID)
        s_pair[0][p] = make_int4(__float_as_int(mE), __float_as_int(mL), ref, 0);
    __syncthreads();

    float fA = 1.f, fB = 1.f, fBs = 0.f;

    // boundary: halo refresh -> window max -> re-base -> factors
    auto boundary = [&](int par) {
        if (lane < KST && p >= 0) {
            int4 h = s_pair[par][p];
            mE = __int_as_float(h.x); mL = __int_as_float(h.y); ref = h.z;
        }
        int fe = max(__float_as_int(mE) >> 23, __float_as_int(mL) >> 23);
        int wm = ref + fe - 127;                 // current exponent (m>=0)
        wm = max(wm, __shfl_up_sync(0xffffffffu, wm, 1));
        wm = max(wm, __shfl_up_sync(0xffffffffu, wm, 2));
        wm = max(wm, __shfl_up_sync(0xffffffffu, wm, 4));   // window 8 lanes
        int refNew = wm + MARGIN;
        int dd = ref - refNew;
        float gA = pw2c(min(max(dd, -127), 127));
        float gB = pw2c(dd - min(max(dd, -127), 127));
        mE = (mE * gA) * gB;  mL = (mL * gA) * gB;
        ref = refNew;
        int r1 = __shfl_up_sync(0xffffffffu, ref, 1);
        int d  = r1 - ref;
        int dA = min(max(d, -127), 127);
        fA = pw2c(dA);  fB = pw2c(d - dA);
        fBs = skip ? fB : 0.f;
    };

    int par = 0;
    int t0 = 1;
    for (; t0 + KST <= tend; t0 += KST, par ^= 1) {
        boundary(par);
        float pyB[KST], pyL[KST];
#pragma unroll
        for (int j = 0; j < KST; ++j) {
            const float* row = s_y[(t0 + j) & (RING - 1)];
            pyB[j] = row[CNUM - 1];
            pyL[j] = row[ext_c];
        }
#pragma unroll
        for (int j = 0; j < KST; ++j) {
            float m1 = __shfl_up_sync(0xffffffffu, mL, 1);
            float tE = m1 * fA;
            float t  = tE * fB;
            float ts = tE * fBs;
            float nE = (mE + t) * pyB[j];
            mL = ((mL + mE) + ts) * pyL[j];
            mE = nE;
        }
        if (lane >= VALID)
            s_pair[par ^ 1][p] = make_int4(__float_as_int(mE), __float_as_int(mL), ref, 0);
        if (loader) {
#pragma unroll
            for (int jj = 0; jj < KST; ++jj) {
                int tn = t0 + PRO - 1 + jj;          // rows t0+25 .. t0+30
                if (tn < T) cp_async16(smy + (uint32_t)((tn & (RING - 1)) * CNUM + lane * 4) * 4,
                                       pb + (size_t)tn * CNUM + lane * 4);
                asm volatile("cp.async.commit_group;");
            }
            asm volatile("cp.async.wait_group 19;");
        }
        __syncthreads();
    }

    // tail (< 6 steps)
    if (t0 < tend) {
        boundary(par);
        for (int t = t0; t < tend; ++t) {
            const float* row = s_y[t & (RING - 1)];
            float pB = row[CNUM - 1], pL = row[ext_c];
            float m1 = __shfl_up_sync(0xffffffffu, mL, 1);
            float tE = m1 * fA;
            float t2 = tE * fB;
            float ts = tE * fBs;
            float nE = (mE + t2) * pB;
            mL = ((mL + mE) + ts) * pL;
            mE = nE;
        }
    }

    // final publish (valid lanes)
    if (lane >= KST) {
        s_al[2 * p]     = make_int2(__float_as_int(mE), ref);
        s_al[2 * p + 1] = make_int2(__float_as_int(mL), ref);
    }
    __syncthreads();

    if (tid == 0) {
        int se = 2 * lab_len[b];
        int sp = (se > 0) ? (se - 1) : 0;
        int2 A = s_al[se];
        int2 P = s_al[sp];
        double va = (double)__int_as_float(A.x);
        double vp = (double)__int_as_float(P.x);
        long long ra = (va > 0.0) ? (long long)A.y : (long long)(-(1ll << 40));
        long long rp = (vp > 0.0) ? (long long)P.y : (long long)(-(1ll << 40));
        long long rm = (ra > rp) ? ra : rp;
        double sum = 0.0;
        if (va > 0.0) sum += va * exp2((double)(ra - rm));
        if (vp > 0.0) sum += vp * exp2((double)(rp - rm));
        out[b] = (float)(-(log(sum) + (double)rm * 0.6931471805599453));
    }
}

// ---------------------------------------------------------------------------
extern "C" void kernel_launch(void* const* d_in, const int* in_sizes, int n_in,
                              void* d_out, int out_size) {
    const float* y  = (const float*)d_in[0];
    const int*   yt = (const int*)d_in[1];
    const int*   il = (const int*)d_in[2];
    const int*   ll = (const int*)d_in[3];
    int B = in_sizes[2];
    int L = in_sizes[1] / B;
    int rows = in_sizes[0] / CNUM;   // B*T
    int T = rows / B;

    int sm_blocks = (rows * 32 + 255) / 256;
    softmax_kernel<<<sm_blocks, 256>>>(y, rows);
    ctc_kernel<<<B, NTH>>>(yt, il, ll, (float*)d_out, T, L);
}